// round 15
// baseline (speedup 1.0000x reference)
#include <cuda_runtime.h>
#include <cuda_fp16.h>
#include <cstdint>
#include <math.h>

#define BATCH 16384
#define TT 7
#define DD 1024
#define HH 512
#define EE 64
#define NF 4
#define G4H 2048              // 4*H
#define KCOMB 1540            // D + H + 4
#define KCOMBP 1568           // padded to multiple of 32

// Output offsets (float32 concat in reference return order)
#define OFF_TOPP  ((size_t)0)
#define OFF_TOPI  ((size_t)131072)
#define OFF_LOSS  ((size_t)262144)
#define OFF_FLOW  ((size_t)262145)
#define OFF_USAGE ((size_t)327681)
#define OFF_ADJ   ((size_t)327745)

// ------------------------- scratch (static, no allocs) -------------------------
__device__ float   d_XS[(size_t)BATCH * TT * G4H];
__device__ float   d_FH[(size_t)BATCH * HH];
__device__ float   d_FLOW[(size_t)BATCH * NF];
__device__ float   d_ADJ[(size_t)BATCH * EE];
__device__ float   d_Cst[(size_t)BATCH * HH];
__device__ float   d_Ha[(size_t)BATCH * HH];
__device__ float   d_Hb[(size_t)BATCH * HH];
// split forms: [Hi fp32][H16 half][L16 half]
__device__ float   d_CtxHi[(size_t)BATCH * TT * DD];
__device__ __half  d_CtxH[(size_t)BATCH * TT * DD];
__device__ __half  d_CtxL[(size_t)BATCH * TT * DD];
__device__ float   d_XHi[(size_t)BATCH * DD];
__device__ __half  d_XH[(size_t)BATCH * DD];
__device__ __half  d_XL[(size_t)BATCH * DD];
__device__ float   d_HaHi[(size_t)BATCH * HH];
__device__ __half  d_HaH[(size_t)BATCH * HH];
__device__ __half  d_HaL[(size_t)BATCH * HH];
__device__ float   d_HbHi[(size_t)BATCH * HH];
__device__ __half  d_HbH[(size_t)BATCH * HH];
__device__ __half  d_HbL[(size_t)BATCH * HH];
__device__ float   d_COMBHi[(size_t)BATCH * KCOMBP];
__device__ __half  d_COMBH[(size_t)BATCH * KCOMBP];
__device__ __half  d_COMBL[(size_t)BATCH * KCOMBP];
__device__ float   d_G1Hi[(size_t)BATCH * DD];
__device__ __half  d_G1H[(size_t)BATCH * DD];
__device__ __half  d_G1L[(size_t)BATCH * DD];
// weights (split)
__device__ float   d_WIH2Hi[(size_t)G4H * DD];
__device__ __half  d_WIH2H[(size_t)G4H * DD];
__device__ __half  d_WIH2L[(size_t)G4H * DD];
__device__ float   d_WHH2Hi[(size_t)G4H * HH];
__device__ __half  d_WHH2H[(size_t)G4H * HH];
__device__ __half  d_WHH2L[(size_t)G4H * HH];
__device__ float   d_FW1Hi[(size_t)HH * DD];
__device__ __half  d_FW1H[(size_t)HH * DD];
__device__ __half  d_FW1L[(size_t)HH * DD];
__device__ float   d_GW1Hi[(size_t)DD * KCOMBP];
__device__ __half  d_GW1H[(size_t)DD * KCOMBP];
__device__ __half  d_GW1L[(size_t)DD * KCOMBP];
__device__ float   d_GW2Hi[(size_t)EE * DD];
__device__ __half  d_GW2H[(size_t)EE * DD];
__device__ __half  d_GW2L[(size_t)EE * DD];
__device__ float   d_BSUM2[G4H];

// ------------------------- helpers -------------------------
__device__ __forceinline__ uint32_t smem_u32(const void* p) {
    uint32_t a;
    asm("{ .reg .u64 t; cvta.to.shared.u64 t, %1; cvt.u32.u64 %0, t; }" : "=r"(a) : "l"(p));
    return a;
}
__device__ __forceinline__ void cp16(uint32_t s, const void* g) {
    asm volatile("cp.async.cg.shared.global [%0], [%1], 16;" :: "r"(s), "l"(g) : "memory");
}
#define CP_COMMIT() asm volatile("cp.async.commit_group;" ::: "memory")
#define CP_WAIT1()  asm volatile("cp.async.wait_group 1;" ::: "memory")
#define CP_WAIT0()  asm volatile("cp.async.wait_group 0;" ::: "memory")

__device__ __forceinline__ void ldsm_x4(uint32_t* r, uint32_t addr) {
    asm volatile("ldmatrix.sync.aligned.m8n8.x4.shared.b16 {%0,%1,%2,%3}, [%4];"
        : "=r"(r[0]), "=r"(r[1]), "=r"(r[2]), "=r"(r[3]) : "r"(addr));
}
__device__ __forceinline__ void ldsm_x2(uint32_t* r, uint32_t addr) {
    asm volatile("ldmatrix.sync.aligned.m8n8.x2.shared.b16 {%0,%1}, [%2];"
        : "=r"(r[0]), "=r"(r[1]) : "r"(addr));
}
__device__ __forceinline__ void mma1688(float* c, const uint32_t* a,
                                        uint32_t b0, uint32_t b1) {
    asm volatile(
        "mma.sync.aligned.m16n8k8.row.col.f32.tf32.tf32.f32 "
        "{%0,%1,%2,%3}, {%4,%5,%6,%7}, {%8,%9}, {%0,%1,%2,%3};"
        : "+f"(c[0]), "+f"(c[1]), "+f"(c[2]), "+f"(c[3])
        : "r"(a[0]), "r"(a[1]), "r"(a[2]), "r"(a[3]), "r"(b0), "r"(b1));
}
__device__ __forceinline__ void mma16816(float* c, const uint32_t* a, const uint32_t* b) {
    asm volatile(
        "mma.sync.aligned.m16n8k16.row.col.f32.f16.f16.f32 "
        "{%0,%1,%2,%3}, {%4,%5,%6,%7}, {%8,%9}, {%0,%1,%2,%3};"
        : "+f"(c[0]), "+f"(c[1]), "+f"(c[2]), "+f"(c[3])
        : "r"(a[0]), "r"(a[1]), "r"(a[2]), "r"(a[3]), "r"(b[0]), "r"(b[1]));
}
__device__ __forceinline__ float tf32_rnd(float v) {
    float r; asm("cvt.rna.tf32.f32 %0, %1;" : "=f"(r) : "f"(v)); return r;
}
__device__ __forceinline__ float sigmoidf(float x) { return 1.f / (1.f + expf(-x)); }

__device__ __forceinline__ void split_store(float v, float* hi, __half* h, __half* l, size_t i) {
    float hh = tf32_rnd(v);
    float ll = tf32_rnd(v - hh);
    hi[i] = hh;
    h[i] = __float2half_rn(hh);
    l[i] = __float2half_rn(ll * 2048.f);
}

template<int BN>
struct GemmCore {
    static constexpr int BM = 128, BK = 32;
    static constexpr int NW = 4 * (BN / 32);
    static constexpr int T = 32 * NW;
    static constexpr int P32 = 144;
    static constexpr int P16 = 80;
    static constexpr int A32SZ = BM * P32;
    static constexpr int B32SZ = BN * P32;
    static constexpr int A16SZ = BM * P16;
    static constexpr int B16SZ = BN * P16;
    static constexpr int OFF_B32  = A32SZ;
    static constexpr int OFF_A16H = OFF_B32 + B32SZ;
    static constexpr int OFF_A16L = OFF_A16H + A16SZ;
    static constexpr int OFF_B16H = OFF_A16L + A16SZ;
    static constexpr int OFF_B16L = OFF_B16H + B16SZ;
    static constexpr int STAGE = OFF_B16L + B16SZ;
};

// ------------------------- cp.async GEMM -------------------------------------
// C = A @ W^T with pre-split operands. hh: tf32 k8; corrections: fp16 k16.
template<int BN>
__global__ void __launch_bounds__(128 * (BN / 32), 1)
gemm_cp(const float* __restrict__ AHi, const __half* __restrict__ AH,
        const __half* __restrict__ AL, int lda,
        const float* __restrict__ WHi, const __half* __restrict__ WH,
        const __half* __restrict__ WL, int ldw,
        float* __restrict__ C, int ldc, int K,
        const float* __restrict__ bias, int relu,
        float* __restrict__ OHi, __half* __restrict__ OH, __half* __restrict__ OL)
{
    using G = GemmCore<BN>;
    extern __shared__ char smem[];
    const uint32_t dsm = smem_u32(smem);

    const int tid = threadIdx.x;
    const int lane = tid & 31;
    const int wid = tid >> 5;
    const int wm = (wid & 3) * 32;
    const int wn = (wid >> 2) * 32;
    const long m0 = (long)blockIdx.y * G::BM;
    const int  n0 = blockIdx.x * BN;

    float Chh[2][4][4], Ccr[2][4][4];
#pragma unroll
    for (int i = 0; i < 2; i++)
#pragma unroll
        for (int j = 0; j < 4; j++)
#pragma unroll
            for (int q = 0; q < 4; q++) { Chh[i][j][q] = 0.f; Ccr[i][j][q] = 0.f; }

    auto issue = [&](int ch) {
        const uint32_t st = dsm + (ch & 1) * G::STAGE;
        const int k0 = ch * G::BK;
        for (int q = tid; q < G::BM * 8; q += G::T) {
            int row = q >> 3, seg = q & 7;
            cp16(st + row * G::P32 + seg * 16,
                 AHi + (m0 + row) * (long)lda + k0 + seg * 4);
        }
        for (int q = tid; q < BN * 8; q += G::T) {
            int row = q >> 3, seg = q & 7;
            cp16(st + G::OFF_B32 + row * G::P32 + seg * 16,
                 WHi + (long)(n0 + row) * ldw + k0 + seg * 4);
        }
        for (int q = tid; q < G::BM * 4; q += G::T) {
            int row = q >> 2, seg = q & 3;
            cp16(st + G::OFF_A16H + row * G::P16 + seg * 16,
                 AH + (m0 + row) * (long)lda + k0 + seg * 8);
            cp16(st + G::OFF_A16L + row * G::P16 + seg * 16,
                 AL + (m0 + row) * (long)lda + k0 + seg * 8);
        }
        for (int q = tid; q < BN * 4; q += G::T) {
            int row = q >> 2, seg = q & 3;
            cp16(st + G::OFF_B16H + row * G::P16 + seg * 16,
                 WH + (long)(n0 + row) * ldw + k0 + seg * 8);
            cp16(st + G::OFF_B16L + row * G::P16 + seg * 16,
                 WL + (long)(n0 + row) * ldw + k0 + seg * 8);
        }
    };

    const uint32_t a32_off = (uint32_t)((lane & 15) * G::P32 + (lane >> 4) * 16);
    const uint32_t b32_off = (uint32_t)((((lane >> 3) & 1) * 8 + (lane & 7)) * G::P32
                                        + (lane >> 4) * 16);
    const int ll = lane & 15;
    const uint32_t a16_off = (uint32_t)((wm + (lane & 15)) * G::P16 + (lane >> 4) * 16);
    const uint32_t b16_off = (uint32_t)((wn + (ll & 7)) * G::P16 + (ll >> 3) * 16);

    auto compute = [&](int s) {
        const uint32_t base = dsm + s * G::STAGE;
        const uint32_t aHp = base + (uint32_t)(wm * G::P32) + a32_off;
        const uint32_t bHp = base + G::OFF_B32 + (uint32_t)(wn * G::P32) + b32_off;
#pragma unroll
        for (int ks = 0; ks < 4; ks++) {
            uint32_t ah[2][4];
            uint32_t bh[4][2];
#pragma unroll
            for (int mi = 0; mi < 2; mi++)
                ldsm_x4(ah[mi], aHp + mi * 16 * G::P32 + ks * 32);
#pragma unroll
            for (int p = 0; p < 2; p++) {
                uint32_t t[4];
                ldsm_x4(t, bHp + p * 16 * G::P32 + ks * 32);
                bh[2*p][0] = t[0]; bh[2*p][1] = t[2];
                bh[2*p+1][0] = t[1]; bh[2*p+1][1] = t[3];
            }
#pragma unroll
            for (int mi = 0; mi < 2; mi++)
#pragma unroll
                for (int ni = 0; ni < 4; ni++)
                    mma1688(Chh[mi][ni], ah[mi], bh[ni][0], bh[ni][1]);
        }
        const uint32_t aHh = base + G::OFF_A16H + a16_off;
        const uint32_t aLh = base + G::OFF_A16L + a16_off;
        const uint32_t bHh = base + G::OFF_B16H + b16_off;
        const uint32_t bLh = base + G::OFF_B16L + b16_off;
#pragma unroll
        for (int ks = 0; ks < 2; ks++) {
            uint32_t ah16[2][4], al16[2][4], bh16[4][2], bl16[4][2];
#pragma unroll
            for (int mi = 0; mi < 2; mi++) {
                ldsm_x4(ah16[mi], aHh + mi * 16 * G::P16 + ks * 32);
                ldsm_x4(al16[mi], aLh + mi * 16 * G::P16 + ks * 32);
            }
#pragma unroll
            for (int ni = 0; ni < 4; ni++) {
                ldsm_x2(bh16[ni], bHh + ni * 8 * G::P16 + ks * 32);
                ldsm_x2(bl16[ni], bLh + ni * 8 * G::P16 + ks * 32);
            }
#pragma unroll
            for (int mi = 0; mi < 2; mi++)
#pragma unroll
                for (int ni = 0; ni < 4; ni++)
                    mma16816(Ccr[mi][ni], ah16[mi], bl16[ni]);
#pragma unroll
            for (int mi = 0; mi < 2; mi++)
#pragma unroll
                for (int ni = 0; ni < 4; ni++)
                    mma16816(Ccr[mi][ni], al16[mi], bh16[ni]);
        }
    };

    const int nch = K / G::BK;
    issue(0); CP_COMMIT();
    if (nch > 1) { issue(1); CP_COMMIT(); }
    for (int i = 0; i < nch; i++) {
        if (i + 1 < nch) CP_WAIT1(); else CP_WAIT0();
        __syncthreads();
        compute(i & 1);
        if (i + 2 < nch) {
            __syncthreads();
            issue(i + 2); CP_COMMIT();
        }
    }

    const float sc = 1.0f / 2048.0f;
#pragma unroll
    for (int mi = 0; mi < 2; mi++)
#pragma unroll
        for (int ni = 0; ni < 4; ni++)
#pragma unroll
            for (int h = 0; h < 2; h++) {
                long row = m0 + wm + mi * 16 + (lane >> 2) + h * 8;
                int  col = n0 + wn + ni * 8 + (lane & 3) * 2;
                float v0 = Chh[mi][ni][2 * h + 0] + sc * Ccr[mi][ni][2 * h + 0];
                float v1 = Chh[mi][ni][2 * h + 1] + sc * Ccr[mi][ni][2 * h + 1];
                if (bias) { v0 += bias[col]; v1 += bias[col + 1]; }
                if (relu) { v0 = fmaxf(v0, 0.f); v1 = fmaxf(v1, 0.f); }
                if (C)
                    *reinterpret_cast<float2*>(C + row * (long)ldc + col) = make_float2(v0, v1);
                if (OHi) {
                    size_t o = row * (size_t)ldc + col;
                    split_store(v0, OHi, OH, OL, o);
                    split_store(v1, OHi, OH, OL, o + 1);
                }
            }
}

// ------------------------- fused recurrent GEMM + LSTM pointwise -------------
__global__ void __launch_bounds__(512, 1)
gemm_lstm(const float* __restrict__ AHi, const __half* __restrict__ AH,
          const __half* __restrict__ AL,
          const float* __restrict__ WHi, const __half* __restrict__ WH,
          const __half* __restrict__ WL,
          const float* __restrict__ addend,   // XS + t*G4H, ld = TT*G4H
          float* __restrict__ Hout, float* __restrict__ HoHi,
          __half* __restrict__ HoH, __half* __restrict__ HoL,
          float* __restrict__ Cs)
{
    using G = GemmCore<128>;
    constexpr int BN = 128;
    extern __shared__ char smem[];
    const uint32_t dsm = smem_u32(smem);

    const int tid = threadIdx.x;
    const int lane = tid & 31;
    const int wid = tid >> 5;
    const int wm = (wid & 3) * 32;
    const int wn = (wid >> 2) * 32;
    const long m0 = (long)blockIdx.y * G::BM;
    const int  n0 = blockIdx.x * BN;

    float Chh[2][4][4], Ccr[2][4][4];
#pragma unroll
    for (int i = 0; i < 2; i++)
#pragma unroll
        for (int j = 0; j < 4; j++)
#pragma unroll
            for (int q = 0; q < 4; q++) { Chh[i][j][q] = 0.f; Ccr[i][j][q] = 0.f; }

    auto issue = [&](int ch) {
        const uint32_t st = dsm + (ch & 1) * G::STAGE;
        const int k0 = ch * G::BK;
        for (int q = tid; q < G::BM * 8; q += G::T) {
            int row = q >> 3, seg = q & 7;
            cp16(st + row * G::P32 + seg * 16,
                 AHi + (m0 + row) * (long)HH + k0 + seg * 4);
        }
        for (int q = tid; q < BN * 8; q += G::T) {
            int row = q >> 3, seg = q & 7;
            cp16(st + G::OFF_B32 + row * G::P32 + seg * 16,
                 WHi + (long)(n0 + row) * HH + k0 + seg * 4);
        }
        for (int q = tid; q < G::BM * 4; q += G::T) {
            int row = q >> 2, seg = q & 3;
            cp16(st + G::OFF_A16H + row * G::P16 + seg * 16,
                 AH + (m0 + row) * (long)HH + k0 + seg * 8);
            cp16(st + G::OFF_A16L + row * G::P16 + seg * 16,
                 AL + (m0 + row) * (long)HH + k0 + seg * 8);
        }
        for (int q = tid; q < BN * 4; q += G::T) {
            int row = q >> 2, seg = q & 3;
            cp16(st + G::OFF_B16H + row * G::P16 + seg * 16,
                 WH + (long)(n0 + row) * HH + k0 + seg * 8);
            cp16(st + G::OFF_B16L + row * G::P16 + seg * 16,
                 WL + (long)(n0 + row) * HH + k0 + seg * 8);
        }
    };

    const uint32_t a32_off = (uint32_t)((lane & 15) * G::P32 + (lane >> 4) * 16);
    const uint32_t b32_off = (uint32_t)((((lane >> 3) & 1) * 8 + (lane & 7)) * G::P32
                                        + (lane >> 4) * 16);
    const int ll = lane & 15;
    const uint32_t a16_off = (uint32_t)((wm + (lane & 15)) * G::P16 + (lane >> 4) * 16);
    const uint32_t b16_off = (uint32_t)((wn + (ll & 7)) * G::P16 + (ll >> 3) * 16);

    auto compute = [&](int s) {
        const uint32_t base = dsm + s * G::STAGE;
        const uint32_t aHp = base + (uint32_t)(wm * G::P32) + a32_off;
        const uint32_t bHp = base + G::OFF_B32 + (uint32_t)(wn * G::P32) + b32_off;
#pragma unroll
        for (int ks = 0; ks < 4; ks++) {
            uint32_t ah[2][4];
            uint32_t bh[4][2];
#pragma unroll
            for (int mi = 0; mi < 2; mi++)
                ldsm_x4(ah[mi], aHp + mi * 16 * G::P32 + ks * 32);
#pragma unroll
            for (int p = 0; p < 2; p++) {
                uint32_t t[4];
                ldsm_x4(t, bHp + p * 16 * G::P32 + ks * 32);
                bh[2*p][0] = t[0]; bh[2*p][1] = t[2];
                bh[2*p+1][0] = t[1]; bh[2*p+1][1] = t[3];
            }
#pragma unroll
            for (int mi = 0; mi < 2; mi++)
#pragma unroll
                for (int ni = 0; ni < 4; ni++)
                    mma1688(Chh[mi][ni], ah[mi], bh[ni][0], bh[ni][1]);
        }
        const uint32_t aHh = base + G::OFF_A16H + a16_off;
        const uint32_t aLh = base + G::OFF_A16L + a16_off;
        const uint32_t bHh = base + G::OFF_B16H + b16_off;
        const uint32_t bLh = base + G::OFF_B16L + b16_off;
#pragma unroll
        for (int ks = 0; ks < 2; ks++) {
            uint32_t ah16[2][4], al16[2][4], bh16[4][2], bl16[4][2];
#pragma unroll
            for (int mi = 0; mi < 2; mi++) {
                ldsm_x4(ah16[mi], aHh + mi * 16 * G::P16 + ks * 32);
                ldsm_x4(al16[mi], aLh + mi * 16 * G::P16 + ks * 32);
            }
#pragma unroll
            for (int ni = 0; ni < 4; ni++) {
                ldsm_x2(bh16[ni], bHh + ni * 8 * G::P16 + ks * 32);
                ldsm_x2(bl16[ni], bLh + ni * 8 * G::P16 + ks * 32);
            }
#pragma unroll
            for (int mi = 0; mi < 2; mi++)
#pragma unroll
                for (int ni = 0; ni < 4; ni++)
                    mma16816(Ccr[mi][ni], ah16[mi], bl16[ni]);
#pragma unroll
            for (int mi = 0; mi < 2; mi++)
#pragma unroll
                for (int ni = 0; ni < 4; ni++)
                    mma16816(Ccr[mi][ni], al16[mi], bh16[ni]);
        }
    };

    const int nch = HH / G::BK;  // 16
    issue(0); CP_COMMIT();
    issue(1); CP_COMMIT();
    for (int i = 0; i < nch; i++) {
        if (i + 1 < nch) CP_WAIT1(); else CP_WAIT0();
        __syncthreads();
        compute(i & 1);
        if (i + 2 < nch) {
            __syncthreads();
            issue(i + 2); CP_COMMIT();
        }
    }

    // fused epilogue: gates -> smem -> LSTM pointwise (+ split H out)
    __syncthreads();
    constexpr int GP = 132;
    float* gt = reinterpret_cast<float*>(smem);
    const float sc = 1.0f / 2048.0f;
#pragma unroll
    for (int mi = 0; mi < 2; mi++)
#pragma unroll
        for (int ni = 0; ni < 4; ni++)
#pragma unroll
            for (int h = 0; h < 2; h++) {
                int rl = wm + mi * 16 + (lane >> 2) + h * 8;
                int cl = wn + ni * 8 + (lane & 3) * 2;
                long row = m0 + rl;
                int  col = n0 + cl;
                float2 ad = *reinterpret_cast<const float2*>(
                    addend + row * (long)(TT * G4H) + col);
                gt[rl * GP + cl]     = Chh[mi][ni][2*h+0] + sc * Ccr[mi][ni][2*h+0] + ad.x;
                gt[rl * GP + cl + 1] = Chh[mi][ni][2*h+1] + sc * Ccr[mi][ni][2*h+1] + ad.y;
            }
    __syncthreads();

    const int u0 = n0 >> 2;
    for (int q = tid; q < 128 * 32; q += 512) {
        int r = q >> 5;
        int u = q & 31;
        float4 g4 = *reinterpret_cast<float4*>(gt + r * GP + u * 4);  // i,f,g,o
        size_t idx = (size_t)(m0 + r) * HH + (u0 + u);
        float cold = Cs[idx];
        float c = sigmoidf(g4.y) * cold + sigmoidf(g4.x) * tanhf(g4.z);
        Cs[idx] = c;
        float hval = sigmoidf(g4.w) * tanhf(c);
        Hout[idx] = hval;
        split_store(hval, HoHi, HoH, HoL, idx);
    }
}

// ------------------------- elementwise kernels -------------------------
__global__ void split_flat(const float* __restrict__ src, size_t n,
                           float* __restrict__ hi, __half* __restrict__ h,
                           __half* __restrict__ l) {
    size_t i = (size_t)blockIdx.x * blockDim.x + threadIdx.x;
    if (i >= n) return;
    split_store(src[i], hi, h, l, i);
    // hi written by split_store; ensure hi array gets value (it does)
}

__global__ void split_pad(const float* __restrict__ src, int N, int K, int Kp,
                          float* __restrict__ hi, __half* __restrict__ h,
                          __half* __restrict__ l) {
    size_t i = (size_t)blockIdx.x * blockDim.x + threadIdx.x;
    if (i >= (size_t)N * Kp) return;
    int r = (int)(i / Kp), c = (int)(i % Kp);
    float v = (c < K) ? src[(size_t)r * K + c] : 0.f;
    split_store(v, hi, h, l, i);
}

__global__ void zero_kernel(float* __restrict__ p, size_t n) {
    size_t i = (size_t)blockIdx.x * blockDim.x + threadIdx.x;
    if (i < n) p[i] = 0.f;
}

// permute LSTM weights to gate-interleaved layout + split: n -> 4*(n%512)+n/512
__global__ void perm_kernel(const float* __restrict__ Wih, const float* __restrict__ Whh,
                            const float* __restrict__ bih, const float* __restrict__ bhh) {
    int n = blockIdx.x;
    int np = 4 * (n & 511) + (n >> 9);
    for (int i = threadIdx.x; i < DD; i += blockDim.x)
        split_store(Wih[(size_t)n * DD + i], d_WIH2Hi, d_WIH2H, d_WIH2L, (size_t)np * DD + i);
    for (int i = threadIdx.x; i < HH; i += blockDim.x)
        split_store(Whh[(size_t)n * HH + i], d_WHH2Hi, d_WHH2H, d_WHH2L, (size_t)np * HH + i);
    if (threadIdx.x == 0) d_BSUM2[np] = bih[n] + bhh[n];
}

// t=0 LSTM pointwise on interleaved XS (h0 = c0 = 0) with split H output
__global__ void lstm0_il(const float* __restrict__ XS0, float* __restrict__ Hs,
                         float* __restrict__ HHi, __half* __restrict__ H16,
                         __half* __restrict__ L16, float* __restrict__ Cs) {
    int idx = blockIdx.x * blockDim.x + threadIdx.x;
    if (idx >= BATCH * HH) return;
    int b = idx / HH, j = idx % HH;
    float4 g4 = *reinterpret_cast<const float4*>(XS0 + (size_t)b * (TT * G4H) + 4 * j);
    float c = sigmoidf(g4.x) * tanhf(g4.z);
    Cs[idx] = c;
    float h = sigmoidf(g4.w) * tanhf(c);
    Hs[idx] = h;
    split_store(h, HHi, H16, L16, idx);
}

__global__ void flow2_kernel(const float* __restrict__ FHp,
                             const float* __restrict__ fw2,
                             const float* __restrict__ fb2,
                             float* __restrict__ FLOWp,
                             float* __restrict__ out) {
    __shared__ float w[NF * HH];
    int tid = threadIdx.x;
    for (int q = tid; q < NF * HH; q += blockDim.x) w[q] = fw2[q];
    __syncthreads();
    int warp = tid >> 5, lane = tid & 31;
    int b = blockIdx.x * 8 + warp;
    const float* r = FHp + (size_t)b * HH;
    float a0 = 0.f, a1 = 0.f, a2 = 0.f, a3 = 0.f;
    for (int k = lane; k < HH; k += 32) {
        float v = r[k];
        a0 += v * w[k];
        a1 += v * w[HH + k];
        a2 += v * w[2 * HH + k];
        a3 += v * w[3 * HH + k];
    }
#pragma unroll
    for (int off = 16; off; off >>= 1) {
        a0 += __shfl_xor_sync(0xffffffffu, a0, off);
        a1 += __shfl_xor_sync(0xffffffffu, a1, off);
        a2 += __shfl_xor_sync(0xffffffffu, a2, off);
        a3 += __shfl_xor_sync(0xffffffffu, a3, off);
    }
    if (lane == 0) {
        a0 += fb2[0]; a1 += fb2[1]; a2 += fb2[2]; a3 += fb2[3];
        float m = fmaxf(fmaxf(a0, a1), fmaxf(a2, a3));
        float e0 = expf(a0 - m), e1 = expf(a1 - m), e2 = expf(a2 - m), e3 = expf(a3 - m);
        float inv = 1.f / (e0 + e1 + e2 + e3);
        float p0 = e0 * inv, p1 = e1 * inv, p2 = e2 * inv, p3 = e3 * inv;
        FLOWp[b * 4 + 0] = p0; FLOWp[b * 4 + 1] = p1;
        FLOWp[b * 4 + 2] = p2; FLOWp[b * 4 + 3] = p3;
        out[OFF_FLOW + b * 4 + 0] = p0; out[OFF_FLOW + b * 4 + 1] = p1;
        out[OFF_FLOW + b * 4 + 2] = p2; out[OFF_FLOW + b * 4 + 3] = p3;
    }
}

// build comb (padded) directly in split form
__global__ void build_comb(const float* __restrict__ x,
                           const float* __restrict__ Hs,
                           const float* __restrict__ FLOWp) {
    size_t idx = (size_t)blockIdx.x * blockDim.x + threadIdx.x;
    if (idx >= (size_t)BATCH * KCOMBP) return;
    int b = (int)(idx / KCOMBP), c = (int)(idx % KCOMBP);
    float v;
    if (c < DD)            v = x[(size_t)b * DD + c];
    else if (c < DD + HH)  v = Hs[(size_t)b * HH + (c - DD)];
    else if (c < KCOMB)    v = FLOWp[b * 4 + (c - DD - HH)];
    else                   v = 0.f;
    split_store(v, d_COMBHi, d_COMBH, d_COMBL, idx);
}

__global__ void final_gate_kernel(const float* __restrict__ adjraw,
                                  const float* __restrict__ flow,
                                  const float* __restrict__ spec,
                                  float* __restrict__ out) {
    __shared__ float s_spec[EE * NF];
    __shared__ float s_usage[EE];
    int tid = threadIdx.x;
    if (tid < EE * NF) s_spec[tid] = spec[tid];
    if (tid < EE)      s_usage[tid] = 0.f;
    __syncthreads();

    int warp = tid >> 5, lane = tid & 31;
    int b = blockIdx.x * 8 + warp;

    float f0 = flow[b * 4 + 0], f1 = flow[b * 4 + 1], f2 = flow[b * 4 + 2], f3 = flow[b * 4 + 3];
    int e0 = lane, e1 = lane + 32;
    float sp0 = 0.1f * (f0 * s_spec[e0 * 4 + 0] + f1 * s_spec[e0 * 4 + 1] +
                        f2 * s_spec[e0 * 4 + 2] + f3 * s_spec[e0 * 4 + 3]);
    float sp1 = 0.1f * (f0 * s_spec[e1 * 4 + 0] + f1 * s_spec[e1 * 4 + 1] +
                        f2 * s_spec[e1 * 4 + 2] + f3 * s_spec[e1 * 4 + 3]);
    float l0 = adjraw[(size_t)b * EE + e0] + sp0;
    float l1 = adjraw[(size_t)b * EE + e1] + sp1;
    out[OFF_ADJ + (size_t)b * EE + e0] = l0;
    out[OFF_ADJ + (size_t)b * EE + e1] = l1;

    float m = fmaxf(l0, l1);
#pragma unroll
    for (int off = 16; off; off >>= 1) m = fmaxf(m, __shfl_xor_sync(0xffffffffu, m, off));
    float x0 = expf(l0 - m), x1 = expf(l1 - m);
    float s = x0 + x1;
#pragma unroll
    for (int off = 16; off; off >>= 1) s += __shfl_xor_sync(0xffffffffu, s, off);
    float inv_s = 1.f / s;
    float p0 = x0 * inv_s, p1 = x1 * inv_s;

    atomicAdd(&s_usage[e0], p0);
    atomicAdd(&s_usage[e1], p1);

    float tp[8]; int ti[8];
    float v0 = p0, v1 = p1;
#pragma unroll
    for (int it = 0; it < 8; it++) {
        float v; int bi;
        if (v1 > v0) { v = v1; bi = e1; } else { v = v0; bi = e0; }
#pragma unroll
        for (int off = 16; off; off >>= 1) {
            float ov = __shfl_xor_sync(0xffffffffu, v, off);
            int   oi = __shfl_xor_sync(0xffffffffu, bi, off);
            if (ov > v || (ov == v && oi < bi)) { v = ov; bi = oi; }
        }
        tp[it] = v; ti[it] = bi;
        if (bi == e0) v0 = -1.f;
        if (bi == e1) v1 = -1.f;
    }
    float ssum = 0.f;
#pragma unroll
    for (int it = 0; it < 8; it++) ssum += tp[it];
    float invn = 1.f / (ssum + 1e-8f);
    if (lane < 8) {
        out[OFF_TOPP + (size_t)b * 8 + lane] = tp[lane] * invn;
        out[OFF_TOPI + (size_t)b * 8 + lane] = (float)ti[lane];
    }
    __syncthreads();
    if (tid < EE) atomicAdd(&out[OFF_USAGE + tid], s_usage[tid]);
}

__global__ void loss_kernel(float* __restrict__ out) {
    __shared__ float red[EE];
    int t = threadIdx.x;
    float u = out[OFF_USAGE + t] / (float)BATCH;
    out[OFF_USAGE + t] = u;
    red[t] = -(1.0f / 64.f) * log1pf(64.f * u - 1.f);
    __syncthreads();
    for (int s = 32; s; s >>= 1) {
        if (t < s) red[t] += red[t + s];
        __syncthreads();
    }
    if (t == 0) out[OFF_LOSS] = red[0] / 64.f;
}

// ------------------------- launch -------------------------
extern "C" void kernel_launch(void* const* d_in, const int* in_sizes, int n_in,
                              void* d_out, int out_size) {
    const float* x        = (const float*)d_in[0];
    const float* context  = (const float*)d_in[1];
    const float* W_ih     = (const float*)d_in[2];
    const float* W_hh     = (const float*)d_in[3];
    const float* b_ih     = (const float*)d_in[4];
    const float* b_hh     = (const float*)d_in[5];
    const float* fw1      = (const float*)d_in[6];
    const float* fb1      = (const float*)d_in[7];
    const float* fw2      = (const float*)d_in[8];
    const float* fb2      = (const float*)d_in[9];
    const float* gw1      = (const float*)d_in[10];
    const float* gb1      = (const float*)d_in[11];
    const float* gw2      = (const float*)d_in[12];
    const float* gb2      = (const float*)d_in[13];
    const float* espec    = (const float*)d_in[14];
    float* out = (float*)d_out;

#define SYM(p, s) cudaGetSymbolAddress((void**)&p, s)
    float *XS, *FH, *FLOW, *ADJ, *Cs, *Ha, *Hb, *BSUM2;
    float *CtxHi, *XHi, *HaHi, *HbHi, *COMBHi, *G1Hi;
    float *WIH2Hi, *WHH2Hi, *FW1Hi, *GW1Hi, *GW2Hi;
    __half *CtxH, *CtxL, *XH, *XL, *HaH, *HaL, *HbH, *HbL, *COMBH, *COMBL, *G1H, *G1L;
    __half *WIH2H, *WIH2L, *WHH2H, *WHH2L, *FW1H, *FW1L, *GW1H, *GW1L, *GW2H, *GW2L;
    SYM(XS, d_XS); SYM(FH, d_FH); SYM(FLOW, d_FLOW); SYM(ADJ, d_ADJ);
    SYM(Cs, d_Cst); SYM(Ha, d_Ha); SYM(Hb, d_Hb); SYM(BSUM2, d_BSUM2);
    SYM(CtxHi, d_CtxHi); SYM(CtxH, d_CtxH); SYM(CtxL, d_CtxL);
    SYM(XHi, d_XHi); SYM(XH, d_XH); SYM(XL, d_XL);
    SYM(HaHi, d_HaHi); SYM(HaH, d_HaH); SYM(HaL, d_HaL);
    SYM(HbHi, d_HbHi); SYM(HbH, d_HbH); SYM(HbL, d_HbL);
    SYM(COMBHi, d_COMBHi); SYM(COMBH, d_COMBH); SYM(COMBL, d_COMBL);
    SYM(G1Hi, d_G1Hi); SYM(G1H, d_G1H); SYM(G1L, d_G1L);
    SYM(WIH2Hi, d_WIH2Hi); SYM(WIH2H, d_WIH2H); SYM(WIH2L, d_WIH2L);
    SYM(WHH2Hi, d_WHH2Hi); SYM(WHH2H, d_WHH2H); SYM(WHH2L, d_WHH2L);
    SYM(FW1Hi, d_FW1Hi); SYM(FW1H, d_FW1H); SYM(FW1L, d_FW1L);
    SYM(GW1Hi, d_GW1Hi); SYM(GW1H, d_GW1H); SYM(GW1L, d_GW1L);
    SYM(GW2Hi, d_GW2Hi); SYM(GW2H, d_GW2H); SYM(GW2L, d_GW2L);
#undef SYM

    const int SMEM = 2 * GemmCore<128>::STAGE;       // 155648
    const int SMEM64T = 2 * GemmCore<64>::STAGE;
    cudaFuncSetAttribute(gemm_cp<128>, cudaFuncAttributeMaxDynamicSharedMemorySize, SMEM);
    cudaFuncSetAttribute(gemm_cp<64>,  cudaFuncAttributeMaxDynamicSharedMemorySize, SMEM64T);
    cudaFuncSetAttribute(gemm_lstm,    cudaFuncAttributeMaxDynamicSharedMemorySize, SMEM);

    // 1: permute + split LSTM weights
    perm_kernel<<<G4H, 256>>>(W_ih, W_hh, b_ih, b_hh);

    // 2: split context
    {
        size_t n = (size_t)BATCH * TT * DD;
        split_flat<<<(unsigned)((n + 255) / 256), 256>>>(context, n, CtxHi, CtxH, CtxL);
    }
    // 3: split x
    {
        size_t n = (size_t)BATCH * DD;
        split_flat<<<(unsigned)((n + 255) / 256), 256>>>(x, n, XHi, XH, XL);
    }

    // 4: XS = context @ WIH2^T + BSUM2 (interleaved cols)  <-- profiled slot
    gemm_cp<128><<<dim3(G4H / 128, (BATCH * TT) / 128), 512, SMEM>>>(
        CtxHi, CtxH, CtxL, DD, WIH2Hi, WIH2H, WIH2L, DD,
        XS, G4H, DD, BSUM2, 0, nullptr, nullptr, nullptr);

    // 5: split fw1
    split_flat<<<(unsigned)(((size_t)HH * DD + 255) / 256), 256>>>(
        fw1, (size_t)HH * DD, FW1Hi, FW1H, FW1L);

    // 6: flow hidden: relu(x @ fw1^T + fb1)
    gemm_cp<128><<<dim3(HH / 128, BATCH / 128), 512, SMEM>>>(
        XHi, XH, XL, DD, FW1Hi, FW1H, FW1L, DD,
        FH, HH, DD, fb1, 1, nullptr, nullptr, nullptr);

    // 7: flow softmax head
    flow2_kernel<<<BATCH / 8, 256>>>(FH, fw2, fb2, FLOW, out);

    // 8: t=0 pointwise (h0 = c0 = 0)
    lstm0_il<<<(BATCH * HH + 255) / 256, 256>>>(XS, Ha, HaHi, HaH, HaL, Cs);

    // 9..14: fused recurrent GEMM + LSTM, double-buffered H (splits)
    float *HinF = Ha, *HoutF = Hb;
    float *HinHi = HaHi, *HoutHi = HbHi;
    __half *HinH = HaH, *HoutH = HbH, *HinL = HaL, *HoutL = HbL;
    for (int t = 1; t < TT; t++) {
        gemm_lstm<<<dim3(G4H / 128, BATCH / 128), 512, SMEM>>>(
            HinHi, HinH, HinL, WHH2Hi, WHH2H, WHH2L,
            XS + (size_t)t * G4H, HoutF, HoutHi, HoutH, HoutL, Cs);
        { float* tf = HinF; HinF = HoutF; HoutF = tf; }
        { float* tf = HinHi; HinHi = HoutHi; HoutHi = tf; }
        { __half* th = HinH; HinH = HoutH; HoutH = th; }
        { __half* th = HinL; HinL = HoutL; HoutL = th; }
    }

    // build comb in split form (padded K)
    build_comb<<<(unsigned)(((size_t)BATCH * KCOMBP + 255) / 256), 256>>>(x, HinF, FLOW);

    // split gw1 (padded)
    split_pad<<<(unsigned)(((size_t)DD * KCOMBP + 255) / 256), 256>>>(
        gw1, DD, KCOMB, KCOMBP, GW1Hi, GW1H, GW1L);

    // gate hidden: relu(comb @ gw1^T + gb1), K = 1568 padded; split output G1
    gemm_cp<128><<<dim3(DD / 128, BATCH / 128), 512, SMEM>>>(
        COMBHi, COMBH, COMBL, KCOMBP, GW1Hi, GW1H, GW1L, KCOMBP,
        nullptr, DD, KCOMBP, gb1, 1, G1Hi, G1H, G1L);

    // split gw2
    split_flat<<<(unsigned)(((size_t)EE * DD + 255) / 256), 256>>>(
        gw2, (size_t)EE * DD, GW2Hi, GW2H, GW2L);

    // gate logits: G1 @ gw2^T + gb2
    gemm_cp<64><<<dim3(EE / 64, BATCH / 128), 256, SMEM64T>>>(
        G1Hi, G1H, G1L, DD, GW2Hi, GW2H, GW2L, DD,
        ADJ, EE, DD, gb2, 0, nullptr, nullptr, nullptr);

    zero_kernel<<<1, 64>>>(out + OFF_USAGE, EE);
    final_gate_kernel<<<BATCH / 8, 256>>>(ADJ, FLOW, espec, out);
    loss_kernel<<<1, 64>>>(out);
}

// round 16
// speedup vs baseline: 1.0734x; 1.0734x over previous
#include <cuda_runtime.h>
#include <cuda_fp16.h>
#include <cstdint>
#include <math.h>

#define BATCH 16384
#define TT 7
#define DD 1024
#define HH 512
#define EE 64
#define NF 4
#define G4H 2048              // 4*H
#define KCOMB 1540            // D + H + 4

// Output offsets (float32 concat in reference return order)
#define OFF_TOPP  ((size_t)0)
#define OFF_TOPI  ((size_t)131072)
#define OFF_LOSS  ((size_t)262144)
#define OFF_FLOW  ((size_t)262145)
#define OFF_USAGE ((size_t)327681)
#define OFF_ADJ   ((size_t)327745)

// ------------------------- scratch (static, no allocs) -------------------------
__device__ float d_XS[(size_t)BATCH * TT * G4H];
__device__ float d_Hst[(size_t)BATCH * HH];
__device__ float d_Hst2[(size_t)BATCH * HH];
__device__ float d_Cst[(size_t)BATCH * HH];
__device__ float d_FH[(size_t)BATCH * HH];
__device__ float d_FLOW[(size_t)BATCH * NF];
__device__ float d_COMB[(size_t)BATCH * KCOMB];
__device__ float d_G1[(size_t)BATCH * DD];
__device__ float d_ADJ[(size_t)BATCH * EE];
__device__ float d_WIH2[(size_t)G4H * DD];
__device__ float d_WHH2[(size_t)G4H * HH];
__device__ float d_BSUM2[G4H];

// ------------------------- helpers -------------------------
__device__ __forceinline__ uint32_t smem_u32(const void* p) {
    uint32_t a;
    asm("{ .reg .u64 t; cvta.to.shared.u64 t, %1; cvt.u32.u64 %0, t; }" : "=r"(a) : "l"(p));
    return a;
}
__device__ __forceinline__ void ldsm_x4(uint32_t* r, uint32_t addr) {
    asm volatile("ldmatrix.sync.aligned.m8n8.x4.shared.b16 {%0,%1,%2,%3}, [%4];"
        : "=r"(r[0]), "=r"(r[1]), "=r"(r[2]), "=r"(r[3]) : "r"(addr));
}
__device__ __forceinline__ void mma1688(float* c, const uint32_t* a,
                                        uint32_t b0, uint32_t b1) {
    asm volatile(
        "mma.sync.aligned.m16n8k8.row.col.f32.tf32.tf32.f32 "
        "{%0,%1,%2,%3}, {%4,%5,%6,%7}, {%8,%9}, {%0,%1,%2,%3};"
        : "+f"(c[0]), "+f"(c[1]), "+f"(c[2]), "+f"(c[3])
        : "r"(a[0]), "r"(a[1]), "r"(a[2]), "r"(a[3]), "r"(b0), "r"(b1));
}
__device__ __forceinline__ void mma16816(float* c, const uint32_t* a, const uint32_t* b) {
    asm volatile(
        "mma.sync.aligned.m16n8k16.row.col.f32.f16.f16.f32 "
        "{%0,%1,%2,%3}, {%4,%5,%6,%7}, {%8,%9}, {%0,%1,%2,%3};"
        : "+f"(c[0]), "+f"(c[1]), "+f"(c[2]), "+f"(c[3])
        : "r"(a[0]), "r"(a[1]), "r"(a[2]), "r"(a[3]), "r"(b[0]), "r"(b[1]));
}
__device__ __forceinline__ float tf32_rnd(float v) {
    float r; asm("cvt.rna.tf32.f32 %0, %1;" : "=f"(r) : "f"(v)); return r;
}
__device__ __forceinline__ uint32_t pack2(__half a, __half b) {
    __half2 h = __halves2half2(a, b);
    return *reinterpret_cast<uint32_t*>(&h);
}
__device__ __forceinline__ void tsplit(float v, float& h, float& l) {
    h = tf32_rnd(v);
    l = tf32_rnd(v - h);
}
__device__ __forceinline__ float sigmoidf(float x) { return 1.f / (1.f + expf(-x)); }

// Core geometry: BM=128, BK=32 fp32-k, 256 threads, 8 warps.
// Warp tile 32 x WN (WN=64 for BN=128, WN=32 for BN=64).
template<int BN, int WN>
struct GC {
    static constexpr int BM = 128, BK = 32, T = 256;
    static constexpr int NI = WN / 8;           // B frags per warp
    static constexpr int P32 = 144;
    static constexpr int P16 = 80;
    static constexpr int A32SZ = BM * P32;
    static constexpr int B32SZ = BN * P32;
    static constexpr int A16SZ = BM * P16;
    static constexpr int B16SZ = BN * P16;
    static constexpr int OFF_B32  = A32SZ;
    static constexpr int OFF_A16H = OFF_B32 + B32SZ;
    static constexpr int OFF_A16L = OFF_A16H + A16SZ;
    static constexpr int OFF_B16H = OFF_A16L + A16SZ;
    static constexpr int OFF_B16L = OFF_B16H + B16SZ;
    static constexpr int STAGE = OFF_B16L + B16SZ;
    static constexpr int AV = BM * BK / 4 / T;  // 4
    static constexpr int BV = BN * BK / 4 / T;  // 4 or 2
};

// Shared device machinery: implemented via a macro-free pattern by duplicating
// minimal code inside each kernel (loader/splitter/compute), parameterized on GC.

#define GEMM_BODY(G, WNV, A_, lda_, W_, ldw_, K_)                                        \
    const int tid = threadIdx.x;                                                         \
    const int lane = tid & 31;                                                           \
    const int wid = tid >> 5;                                                            \
    const int wm = (wid & 3) * 32;                                                       \
    const int wn = (wid >> 2) * WNV;                                                     \
    const long m0 = (long)blockIdx.y * G::BM;                                            \
    const int  n0 = blockIdx.x * BN;                                                     \
    float Chh[2][G::NI][4], Ccr[2][G::NI][4];                                            \
    _Pragma("unroll")                                                                    \
    for (int i = 0; i < 2; i++)                                                          \
        _Pragma("unroll")                                                                \
        for (int j = 0; j < G::NI; j++)                                                  \
            _Pragma("unroll")                                                            \
            for (int q = 0; q < 4; q++) { Chh[i][j][q] = 0.f; Ccr[i][j][q] = 0.f; }      \
    float4 ra[G::AV], rb[G::BV];                                                         \
    auto load_chunk = [&](int ch) {                                                      \
        const int k0 = ch * G::BK;                                                       \
        _Pragma("unroll")                                                                \
        for (int q = 0; q < G::AV; q++) {                                                \
            int idx = tid + q * G::T;                                                    \
            int row = idx >> 3, c4 = (idx & 7) * 4;                                      \
            ra[q] = (k0 + c4 < K_)                                                       \
                ? *reinterpret_cast<const float4*>(A_ + (m0 + row) * (long)lda_ + k0 + c4)\
                : make_float4(0.f, 0.f, 0.f, 0.f);                                       \
        }                                                                                \
        _Pragma("unroll")                                                                \
        for (int q = 0; q < G::BV; q++) {                                                \
            int idx = tid + q * G::T;                                                    \
            int row = idx >> 3, c4 = (idx & 7) * 4;                                      \
            rb[q] = (k0 + c4 < K_)                                                       \
                ? *reinterpret_cast<const float4*>(W_ + (long)(n0 + row) * ldw_ + k0 + c4)\
                : make_float4(0.f, 0.f, 0.f, 0.f);                                       \
        }                                                                                \
    };                                                                                   \
    auto store_chunk = [&](int s) {                                                      \
        char* st = smem + s * G::STAGE;                                                  \
        _Pragma("unroll")                                                                \
        for (int q = 0; q < G::AV; q++) {                                                \
            int idx = tid + q * G::T;                                                    \
            int row = idx >> 3, c4 = (idx & 7) * 4;                                      \
            float4 h, l;                                                                 \
            tsplit(ra[q].x, h.x, l.x); tsplit(ra[q].y, h.y, l.y);                        \
            tsplit(ra[q].z, h.z, l.z); tsplit(ra[q].w, h.w, l.w);                        \
            *reinterpret_cast<float4*>(st + row * G::P32 + c4 * 4) = h;                  \
            int o16 = row * G::P16 + c4 * 2;                                             \
            *reinterpret_cast<uint2*>(st + G::OFF_A16H + o16) = make_uint2(              \
                pack2(__float2half_rn(h.x), __float2half_rn(h.y)),                       \
                pack2(__float2half_rn(h.z), __float2half_rn(h.w)));                      \
            *reinterpret_cast<uint2*>(st + G::OFF_A16L + o16) = make_uint2(              \
                pack2(__float2half_rn(l.x * 2048.f), __float2half_rn(l.y * 2048.f)),     \
                pack2(__float2half_rn(l.z * 2048.f), __float2half_rn(l.w * 2048.f)));    \
        }                                                                                \
        _Pragma("unroll")                                                                \
        for (int q = 0; q < G::BV; q++) {                                                \
            int idx = tid + q * G::T;                                                    \
            int row = idx >> 3, c4 = (idx & 7) * 4;                                      \
            float4 h, l;                                                                 \
            tsplit(rb[q].x, h.x, l.x); tsplit(rb[q].y, h.y, l.y);                        \
            tsplit(rb[q].z, h.z, l.z); tsplit(rb[q].w, h.w, l.w);                        \
            *reinterpret_cast<float4*>(st + G::OFF_B32 + row * G::P32 + c4 * 4) = h;     \
            int o16 = row * G::P16 + c4 * 2;                                             \
            *reinterpret_cast<uint2*>(st + G::OFF_B16H + o16) = make_uint2(              \
                pack2(__float2half_rn(h.x), __float2half_rn(h.y)),                       \
                pack2(__float2half_rn(h.z), __float2half_rn(h.w)));                      \
            *reinterpret_cast<uint2*>(st + G::OFF_B16L + o16) = make_uint2(              \
                pack2(__float2half_rn(l.x * 2048.f), __float2half_rn(l.y * 2048.f)),     \
                pack2(__float2half_rn(l.z * 2048.f), __float2half_rn(l.w * 2048.f)));    \
        }                                                                                \
    };                                                                                   \
    const uint32_t lquad = (uint32_t)((lane & 15));                                      \
    const uint32_t lhalf = (uint32_t)(lane >> 4);                                        \
    auto compute = [&](int s) {                                                          \
        const uint32_t base = dsm + s * G::STAGE;                                        \
        const uint32_t aHp = base + (uint32_t)((wm + lquad) * G::P32) + lhalf * 16;      \
        const uint32_t bHp = base + G::OFF_B32 + (uint32_t)((wn + lquad) * G::P32)       \
                           + lhalf * 16;                                                 \
        _Pragma("unroll")                                                                \
        for (int ks = 0; ks < 4; ks++) {                                                 \
            uint32_t ah[2][4];                                                           \
            uint32_t bh[G::NI][2];                                                       \
            _Pragma("unroll")                                                            \
            for (int mi = 0; mi < 2; mi++)                                               \
                ldsm_x4(ah[mi], aHp + mi * 16 * G::P32 + ks * 32);                       \
            _Pragma("unroll")                                                            \
            for (int p = 0; p < G::NI / 2; p++) {                                        \
                uint32_t t[4];                                                           \
                ldsm_x4(t, bHp + p * 16 * G::P32 + ks * 32);                             \
                bh[2*p][0] = t[0]; bh[2*p][1] = t[2];                                    \
                bh[2*p+1][0] = t[1]; bh[2*p+1][1] = t[3];                                \
            }                                                                            \
            _Pragma("unroll")                                                            \
            for (int mi = 0; mi < 2; mi++)                                               \
                _Pragma("unroll")                                                        \
                for (int ni = 0; ni < G::NI; ni++)                                       \
                    mma1688(Chh[mi][ni], ah[mi], bh[ni][0], bh[ni][1]);                  \
        }                                                                                \
        const uint32_t aHh = base + G::OFF_A16H + (uint32_t)((wm + lquad) * G::P16)      \
                           + lhalf * 16;                                                 \
        const uint32_t aLh = aHh + (G::OFF_A16L - G::OFF_A16H);                          \
        const uint32_t bHh = base + G::OFF_B16H + (uint32_t)((wn + lquad) * G::P16)      \
                           + lhalf * 16;                                                 \
        const uint32_t bLh = bHh + (G::OFF_B16L - G::OFF_B16H);                          \
        _Pragma("unroll")                                                                \
        for (int ks = 0; ks < 2; ks++) {                                                 \
            uint32_t ah16[2][4], al16[2][4];                                             \
            uint32_t bh16[G::NI][2], bl16[G::NI][2];                                     \
            _Pragma("unroll")                                                            \
            for (int mi = 0; mi < 2; mi++) {                                             \
                ldsm_x4(ah16[mi], aHh + mi * 16 * G::P16 + ks * 32);                     \
                ldsm_x4(al16[mi], aLh + mi * 16 * G::P16 + ks * 32);                     \
            }                                                                            \
            _Pragma("unroll")                                                            \
            for (int p = 0; p < G::NI / 2; p++) {                                        \
                uint32_t t[4];                                                           \
                ldsm_x4(t, bHh + p * 16 * G::P16 + ks * 32);                             \
                bh16[2*p][0] = t[0]; bh16[2*p][1] = t[2];                                \
                bh16[2*p+1][0] = t[1]; bh16[2*p+1][1] = t[3];                            \
                ldsm_x4(t, bLh + p * 16 * G::P16 + ks * 32);                             \
                bl16[2*p][0] = t[0]; bl16[2*p][1] = t[2];                                \
                bl16[2*p+1][0] = t[1]; bl16[2*p+1][1] = t[3];                            \
            }                                                                            \
            _Pragma("unroll")                                                            \
            for (int mi = 0; mi < 2; mi++)                                               \
                _Pragma("unroll")                                                        \
                for (int ni = 0; ni < G::NI; ni++)                                       \
                    mma16816(Ccr[mi][ni], ah16[mi], bl16[ni]);                           \
            _Pragma("unroll")                                                            \
            for (int mi = 0; mi < 2; mi++)                                               \
                _Pragma("unroll")                                                        \
                for (int ni = 0; ni < G::NI; ni++)                                       \
                    mma16816(Ccr[mi][ni], al16[mi], bh16[ni]);                           \
        }                                                                                \
    };                                                                                   \
    const int nch = (K_ + G::BK - 1) / G::BK;                                            \
    load_chunk(0);                                                                       \
    store_chunk(0);                                                                      \
    __syncthreads();                                                                     \
    for (int i = 0; i < nch; i++) {                                                      \
        const int s = i & 1;                                                             \
        if (i + 1 < nch) load_chunk(i + 1);                                              \
        compute(s);                                                                      \
        if (i + 1 < nch) {                                                               \
            store_chunk(s ^ 1);                                                          \
            __syncthreads();                                                             \
        }                                                                                \
    }

// ------------------------- generic GEMM -------------------------
template<int BN, int WN>
__global__ void __launch_bounds__(256, 1)
gemm_mma(const float* __restrict__ A, int lda,
         const float* __restrict__ W, int ldw,
         float* __restrict__ C, int ldc, int K,
         const float* __restrict__ bias,
         const float* __restrict__ bias2,
         int relu)
{
    using G = GC<BN, WN>;
    extern __shared__ char smem[];
    const uint32_t dsm = smem_u32(smem);
    GEMM_BODY(G, WN, A, lda, W, ldw, K)

    const float sc = 1.0f / 2048.0f;
#pragma unroll
    for (int mi = 0; mi < 2; mi++)
#pragma unroll
        for (int ni = 0; ni < G::NI; ni++)
#pragma unroll
            for (int h = 0; h < 2; h++) {
                long row = m0 + wm + mi * 16 + (lane >> 2) + h * 8;
                int  col = n0 + wn + ni * 8 + (lane & 3) * 2;
                float v0 = Chh[mi][ni][2 * h + 0] + sc * Ccr[mi][ni][2 * h + 0];
                float v1 = Chh[mi][ni][2 * h + 1] + sc * Ccr[mi][ni][2 * h + 1];
                if (bias)  { v0 += bias[col];  v1 += bias[col + 1]; }
                if (bias2) { v0 += bias2[col]; v1 += bias2[col + 1]; }
                if (relu)  { v0 = fmaxf(v0, 0.f); v1 = fmaxf(v1, 0.f); }
                *reinterpret_cast<float2*>(C + row * (long)ldc + col) = make_float2(v0, v1);
            }
}

// ------------------------- fused recurrent GEMM + LSTM pointwise -------------
__global__ void __launch_bounds__(256, 1)
gemm_lstm(const float* __restrict__ Hin,
          const float* __restrict__ Whh,
          const float* __restrict__ addend,   // XS + t*G4H, ld = TT*G4H
          float* __restrict__ Hout,
          float* __restrict__ Cs)
{
    constexpr int BN = 128;
    using G = GC<128, 64>;
    extern __shared__ char smem[];
    const uint32_t dsm = smem_u32(smem);
    GEMM_BODY(G, 64, Hin, HH, Whh, HH, HH)

    // fused epilogue: gates -> smem -> LSTM pointwise
    __syncthreads();
    constexpr int GP = 132;
    float* gt = reinterpret_cast<float*>(smem);
    const float sc = 1.0f / 2048.0f;
#pragma unroll
    for (int mi = 0; mi < 2; mi++)
#pragma unroll
        for (int ni = 0; ni < G::NI; ni++)
#pragma unroll
            for (int h = 0; h < 2; h++) {
                int rl = wm + mi * 16 + (lane >> 2) + h * 8;
                int cl = wn + ni * 8 + (lane & 3) * 2;
                long row = m0 + rl;
                int  col = n0 + cl;
                float2 ad = *reinterpret_cast<const float2*>(
                    addend + row * (long)(TT * G4H) + col);
                gt[rl * GP + cl]     = Chh[mi][ni][2*h+0] + sc * Ccr[mi][ni][2*h+0] + ad.x;
                gt[rl * GP + cl + 1] = Chh[mi][ni][2*h+1] + sc * Ccr[mi][ni][2*h+1] + ad.y;
            }
    __syncthreads();

    const int u0 = n0 >> 2;
    for (int q = tid; q < 128 * 32; q += 256) {
        int r = q >> 5;
        int u = q & 31;
        float4 g4 = *reinterpret_cast<float4*>(gt + r * GP + u * 4);  // i,f,g,o
        size_t idx = (size_t)(m0 + r) * HH + (u0 + u);
        float cold = Cs[idx];
        float c = sigmoidf(g4.y) * cold + sigmoidf(g4.x) * tanhf(g4.z);
        Cs[idx] = c;
        Hout[idx] = sigmoidf(g4.w) * tanhf(c);
    }
}

// ------------------------- small kernels -------------------------
__global__ void zero_kernel(float* __restrict__ p, size_t n) {
    size_t i = (size_t)blockIdx.x * blockDim.x + threadIdx.x;
    if (i < n) p[i] = 0.f;
}

// permute LSTM weights to gate-interleaved layout: n -> 4*(n%512) + n/512
__global__ void perm_kernel(const float* __restrict__ Wih, const float* __restrict__ Whh,
                            const float* __restrict__ bih, const float* __restrict__ bhh,
                            float* __restrict__ Wih2, float* __restrict__ Whh2,
                            float* __restrict__ bsum2) {
    int n = blockIdx.x;
    int np = 4 * (n & 511) + (n >> 9);
    for (int i = threadIdx.x; i < DD; i += blockDim.x)
        Wih2[(size_t)np * DD + i] = Wih[(size_t)n * DD + i];
    for (int i = threadIdx.x; i < HH; i += blockDim.x)
        Whh2[(size_t)np * HH + i] = Whh[(size_t)n * HH + i];
    if (threadIdx.x == 0) bsum2[np] = bih[n] + bhh[n];
}

// t=0 LSTM pointwise on interleaved XS (h0 = c0 = 0)
__global__ void lstm0_il(const float* __restrict__ XS0, float* __restrict__ Hs,
                         float* __restrict__ Cs) {
    int idx = blockIdx.x * blockDim.x + threadIdx.x;
    if (idx >= BATCH * HH) return;
    int b = idx / HH, j = idx % HH;
    float4 g4 = *reinterpret_cast<const float4*>(XS0 + (size_t)b * (TT * G4H) + 4 * j);
    float c = sigmoidf(g4.x) * tanhf(g4.z);
    Cs[idx] = c;
    Hs[idx] = sigmoidf(g4.w) * tanhf(c);
}

__global__ void flow2_kernel(const float* __restrict__ FHp,
                             const float* __restrict__ fw2,
                             const float* __restrict__ fb2,
                             float* __restrict__ FLOWp,
                             float* __restrict__ out) {
    __shared__ float w[NF * HH];
    int tid = threadIdx.x;
    for (int q = tid; q < NF * HH; q += blockDim.x) w[q] = fw2[q];
    __syncthreads();
    int warp = tid >> 5, lane = tid & 31;
    int b = blockIdx.x * 8 + warp;
    const float* r = FHp + (size_t)b * HH;
    float a0 = 0.f, a1 = 0.f, a2 = 0.f, a3 = 0.f;
    for (int k = lane; k < HH; k += 32) {
        float v = r[k];
        a0 += v * w[k];
        a1 += v * w[HH + k];
        a2 += v * w[2 * HH + k];
        a3 += v * w[3 * HH + k];
    }
#pragma unroll
    for (int off = 16; off; off >>= 1) {
        a0 += __shfl_xor_sync(0xffffffffu, a0, off);
        a1 += __shfl_xor_sync(0xffffffffu, a1, off);
        a2 += __shfl_xor_sync(0xffffffffu, a2, off);
        a3 += __shfl_xor_sync(0xffffffffu, a3, off);
    }
    if (lane == 0) {
        a0 += fb2[0]; a1 += fb2[1]; a2 += fb2[2]; a3 += fb2[3];
        float m = fmaxf(fmaxf(a0, a1), fmaxf(a2, a3));
        float e0 = expf(a0 - m), e1 = expf(a1 - m), e2 = expf(a2 - m), e3 = expf(a3 - m);
        float inv = 1.f / (e0 + e1 + e2 + e3);
        float p0 = e0 * inv, p1 = e1 * inv, p2 = e2 * inv, p3 = e3 * inv;
        FLOWp[b * 4 + 0] = p0; FLOWp[b * 4 + 1] = p1;
        FLOWp[b * 4 + 2] = p2; FLOWp[b * 4 + 3] = p3;
        out[OFF_FLOW + b * 4 + 0] = p0; out[OFF_FLOW + b * 4 + 1] = p1;
        out[OFF_FLOW + b * 4 + 2] = p2; out[OFF_FLOW + b * 4 + 3] = p3;
    }
}

__global__ void build_comb(const float* __restrict__ x,
                           const float* __restrict__ Hs,
                           const float* __restrict__ FLOWp,
                           float* __restrict__ comb) {
    size_t idx = (size_t)blockIdx.x * blockDim.x + threadIdx.x;
    if (idx >= (size_t)BATCH * KCOMB) return;
    int b = (int)(idx / KCOMB), c = (int)(idx % KCOMB);
    float v;
    if (c < DD)            v = x[(size_t)b * DD + c];
    else if (c < DD + HH)  v = Hs[(size_t)b * HH + (c - DD)];
    else                   v = FLOWp[b * 4 + (c - DD - HH)];
    comb[idx] = v;
}

__global__ void final_gate_kernel(const float* __restrict__ adjraw,
                                  const float* __restrict__ flow,
                                  const float* __restrict__ spec,
                                  float* __restrict__ out) {
    __shared__ float s_spec[EE * NF];
    __shared__ float s_usage[EE];
    int tid = threadIdx.x;
    if (tid < EE * NF) s_spec[tid] = spec[tid];
    if (tid < EE)      s_usage[tid] = 0.f;
    __syncthreads();

    int warp = tid >> 5, lane = tid & 31;
    int b = blockIdx.x * 8 + warp;

    float f0 = flow[b * 4 + 0], f1 = flow[b * 4 + 1], f2 = flow[b * 4 + 2], f3 = flow[b * 4 + 3];
    int e0 = lane, e1 = lane + 32;
    float sp0 = 0.1f * (f0 * s_spec[e0 * 4 + 0] + f1 * s_spec[e0 * 4 + 1] +
                        f2 * s_spec[e0 * 4 + 2] + f3 * s_spec[e0 * 4 + 3]);
    float sp1 = 0.1f * (f0 * s_spec[e1 * 4 + 0] + f1 * s_spec[e1 * 4 + 1] +
                        f2 * s_spec[e1 * 4 + 2] + f3 * s_spec[e1 * 4 + 3]);
    float l0 = adjraw[(size_t)b * EE + e0] + sp0;
    float l1 = adjraw[(size_t)b * EE + e1] + sp1;
    out[OFF_ADJ + (size_t)b * EE + e0] = l0;
    out[OFF_ADJ + (size_t)b * EE + e1] = l1;

    float m = fmaxf(l0, l1);
#pragma unroll
    for (int off = 16; off; off >>= 1) m = fmaxf(m, __shfl_xor_sync(0xffffffffu, m, off));
    float x0 = expf(l0 - m), x1 = expf(l1 - m);
    float s = x0 + x1;
#pragma unroll
    for (int off = 16; off; off >>= 1) s += __shfl_xor_sync(0xffffffffu, s, off);
    float inv_s = 1.f / s;
    float p0 = x0 * inv_s, p1 = x1 * inv_s;

    atomicAdd(&s_usage[e0], p0);
    atomicAdd(&s_usage[e1], p1);

    float tp[8]; int ti[8];
    float v0 = p0, v1 = p1;
#pragma unroll
    for (int it = 0; it < 8; it++) {
        float v; int bi;
        if (v1 > v0) { v = v1; bi = e1; } else { v = v0; bi = e0; }
#pragma unroll
        for (int off = 16; off; off >>= 1) {
            float ov = __shfl_xor_sync(0xffffffffu, v, off);
            int   oi = __shfl_xor_sync(0xffffffffu, bi, off);
            if (ov > v || (ov == v && oi < bi)) { v = ov; bi = oi; }
        }
        tp[it] = v; ti[it] = bi;
        if (bi == e0) v0 = -1.f;
        if (bi == e1) v1 = -1.f;
    }
    float ssum = 0.f;
#pragma unroll
    for (int it = 0; it < 8; it++) ssum += tp[it];
    float invn = 1.f / (ssum + 1e-8f);
    if (lane < 8) {
        out[OFF_TOPP + (size_t)b * 8 + lane] = tp[lane] * invn;
        out[OFF_TOPI + (size_t)b * 8 + lane] = (float)ti[lane];
    }
    __syncthreads();
    if (tid < EE) atomicAdd(&out[OFF_USAGE + tid], s_usage[tid]);
}

__global__ void loss_kernel(float* __restrict__ out) {
    __shared__ float red[EE];
    int t = threadIdx.x;
    float u = out[OFF_USAGE + t] / (float)BATCH;
    out[OFF_USAGE + t] = u;
    red[t] = -(1.0f / 64.f) * log1pf(64.f * u - 1.f);
    __syncthreads();
    for (int s = 32; s; s >>= 1) {
        if (t < s) red[t] += red[t + s];
        __syncthreads();
    }
    if (t == 0) out[OFF_LOSS] = red[0] / 64.f;
}

// ------------------------- launch -------------------------
extern "C" void kernel_launch(void* const* d_in, const int* in_sizes, int n_in,
                              void* d_out, int out_size) {
    const float* x        = (const float*)d_in[0];
    const float* context  = (const float*)d_in[1];
    const float* W_ih     = (const float*)d_in[2];
    const float* W_hh     = (const float*)d_in[3];
    const float* b_ih     = (const float*)d_in[4];
    const float* b_hh     = (const float*)d_in[5];
    const float* fw1      = (const float*)d_in[6];
    const float* fb1      = (const float*)d_in[7];
    const float* fw2      = (const float*)d_in[8];
    const float* fb2      = (const float*)d_in[9];
    const float* gw1      = (const float*)d_in[10];
    const float* gb1      = (const float*)d_in[11];
    const float* gw2      = (const float*)d_in[12];
    const float* gb2      = (const float*)d_in[13];
    const float* espec    = (const float*)d_in[14];
    float* out = (float*)d_out;

    float *XS, *Ha, *Hb, *Cs, *FH, *FLOW, *COMB, *G1, *ADJ, *WIH2, *WHH2, *BSUM2;
    cudaGetSymbolAddress((void**)&XS,    d_XS);
    cudaGetSymbolAddress((void**)&Ha,    d_Hst);
    cudaGetSymbolAddress((void**)&Hb,    d_Hst2);
    cudaGetSymbolAddress((void**)&Cs,    d_Cst);
    cudaGetSymbolAddress((void**)&FH,    d_FH);
    cudaGetSymbolAddress((void**)&FLOW,  d_FLOW);
    cudaGetSymbolAddress((void**)&COMB,  d_COMB);
    cudaGetSymbolAddress((void**)&G1,    d_G1);
    cudaGetSymbolAddress((void**)&ADJ,   d_ADJ);
    cudaGetSymbolAddress((void**)&WIH2,  d_WIH2);
    cudaGetSymbolAddress((void**)&WHH2,  d_WHH2);
    cudaGetSymbolAddress((void**)&BSUM2, d_BSUM2);

    const int SMEM128 = 2 * GC<128, 64>::STAGE;   // 155648
    const int SMEM64  = 2 * GC<64, 32>::STAGE;
    cudaFuncSetAttribute((void*)gemm_mma<128, 64>,
                         cudaFuncAttributeMaxDynamicSharedMemorySize, SMEM128);
    cudaFuncSetAttribute((void*)gemm_mma<64, 32>,
                         cudaFuncAttributeMaxDynamicSharedMemorySize, SMEM64);
    cudaFuncSetAttribute((void*)gemm_lstm,
                         cudaFuncAttributeMaxDynamicSharedMemorySize, SMEM128);

    // 1: permute LSTM weights + bias to gate-interleaved layout
    perm_kernel<<<G4H, 256>>>(W_ih, W_hh, b_ih, b_hh, WIH2, WHH2, BSUM2);

    // 2: flow hidden: relu(x @ fw1^T + fb1)
    gemm_mma<128, 64><<<dim3(HH / 128, BATCH / 128), 256, SMEM128>>>(
        x, DD, fw1, DD, FH, HH, DD, fb1, nullptr, 1);

    // 3: flow_state softmax head
    flow2_kernel<<<BATCH / 8, 256>>>(FH, fw2, fb2, FLOW, out);

    // 4: XS = context @ WIH2^T + BSUM2 (interleaved cols)  <-- profiled slot
    gemm_mma<128, 64><<<dim3(G4H / 128, (BATCH * TT) / 128), 256, SMEM128>>>(
        context, DD, WIH2, DD, XS, G4H, DD, BSUM2, nullptr, 0);

    // 5: t = 0 pointwise (h0 = c0 = 0), interleaved XS
    lstm0_il<<<(BATCH * HH + 255) / 256, 256>>>(XS, Ha, Cs);

    // 6..12: fused recurrent GEMM + LSTM pointwise, double-buffered H
    float* Hin = Ha;
    float* Hout = Hb;
    for (int t = 1; t < TT; t++) {
        gemm_lstm<<<dim3(G4H / 128, BATCH / 128), 256, SMEM128>>>(
            Hin, WHH2, XS + (size_t)t * G4H, Hout, Cs);
        float* tmp = Hin; Hin = Hout; Hout = tmp;
    }

    build_comb<<<(unsigned)(((size_t)BATCH * KCOMB + 255) / 256), 256>>>(x, Hin, FLOW, COMB);

    // gate hidden: relu(combined @ gw1^T + gb1), K = 1540 (ragged last chunk)
    gemm_mma<128, 64><<<dim3(DD / 128, BATCH / 128), 256, SMEM128>>>(
        COMB, KCOMB, gw1, KCOMB, G1, DD, KCOMB, gb1, nullptr, 1);

    // gate logits: G1 @ gw2^T + gb2
    gemm_mma<64, 32><<<dim3(EE / 64, BATCH / 128), 256, SMEM64>>>(
        G1, DD, gw2, DD, ADJ, EE, DD, gb2, nullptr, 0);

    zero_kernel<<<1, 64>>>(out + OFF_USAGE, EE);
    final_gate_kernel<<<BATCH / 8, 256>>>(ADJ, FLOW, espec, out);
    loss_kernel<<<1, 64>>>(out);
}